// round 15
// baseline (speedup 1.0000x reference)
#include <cuda_runtime.h>
#include <cuda_fp16.h>
#include <cstdint>

// ---------------------------------------------------------------------------
// LaplacianPyramid, unified-table with row-pair QUAD tiles.
//
// F = f1+f2+f3+f4 is exactly piecewise-bilinear on the uniform m/4096 uv-grid.
// Table: Q[t][x] = (K[2t][x], K[2t][x+1], K[2t+1][x], K[2t+1][x+1]) as 4xfp16
// (8 B, stored/loaded as uint2). Even y0 pixels: ONE 8B load (both rows in one
// sector). Odd y0: two. Average 1.5 sectors/pixel vs 2.0 for the row-pair
// layout -> 25% less L2 traffic on a kernel near the LTS throughput cap.
// ---------------------------------------------------------------------------

__device__ uint2 g_Q[2049 * 4096];  // 67.1 MB (tile 2048 row1 = zeros, unread)

__device__ __forceinline__ float2 h2f(uint32_t w) {
    __half2 h = *reinterpret_cast<__half2*>(&w);
    return __half22float2(h);
}

// ---- generic small layer (S in {1024,512,256}): 3 source cols ----
template <int S>
struct SL {
    const float* src;
    int c0;
    float wx[5];
    int tmask;
    bool ok0, ok1, ok2;
    float ha[5], hb[5];
    int prev_y0;

    __device__ __forceinline__ void setup(const float* s, int x4) {
        src = s;
        const float sc = (float)S / 4096.f;
        c0 = (int)floorf((float)x4 * sc - 0.5f);
        tmask = 0;
#pragma unroll
        for (int k = 0; k < 5; k++) {
            float xs = fmaf((float)(x4 + k), sc, -0.5f);
            float x0 = floorf(xs);
            wx[k] = xs - x0;
            if ((int)x0 != c0) tmask |= (1 << k);
        }
        ok0 = (c0 >= 0) & (c0 < S);
        ok1 = (c0 + 1 >= 0) & (c0 + 1 < S);
        ok2 = (c0 + 2 >= 0) & (c0 + 2 < S);
    }
    __device__ __forceinline__ void load_row(int row, float* h) {
        float s0 = 0.f, s1 = 0.f, s2 = 0.f;
        if (row >= 0 && row < S) {
            const float* r = src + (long long)row * S + c0;
            if (ok0) s0 = __ldcs(r);
            if (ok1) s1 = __ldcs(r + 1);
            if (ok2) s2 = __ldcs(r + 2);
        }
#pragma unroll
        for (int k = 0; k < 5; k++) {
            bool t = (tmask >> k) & 1;
            float v0 = t ? s1 : s0;
            float v1 = t ? s2 : s1;
            h[k] = fmaf(wx[k], v1 - v0, v0);
        }
    }
    __device__ __forceinline__ void init(int n) {
        const float sc = (float)S / 4096.f;
        prev_y0 = (int)floorf(fmaf((float)n, sc, -0.5f));
        load_row(prev_y0, ha);
        load_row(prev_y0 + 1, hb);
    }
    __device__ __forceinline__ float wy_adv(int n) {
        const float sc = (float)S / 4096.f;
        float y = fmaf((float)n, sc, -0.5f);
        float y0f = floorf(y);
        int y0 = (int)y0f;
        if (y0 != prev_y0) {
#pragma unroll
            for (int k = 0; k < 5; k++) ha[k] = hb[k];
            load_row(y0 + 1, hb);
            prev_y0 = y0;
        }
        return y - y0f;
    }
};

// ---- layer1 (S=2048): fixed copy/average pattern ----
struct L1S {
    const float* src;
    int j;
    bool okA, okD;
    float ha[5], hb[5];
    int prev_y0;

    __device__ __forceinline__ void setup(const float* s, int x4) {
        src = s;
        j = x4 >> 1;
        okA = (j - 1 >= 0);
        okD = (j + 2 < 2048);
    }
    __device__ __forceinline__ void load_row(int row, float* h) {
        float s0 = 0.f, s1 = 0.f, s2 = 0.f, s3 = 0.f;
        if (row >= 0 && row < 2048) {
            const float* r = src + (long long)row * 2048 + j;
            s1 = __ldcs(r);
            s2 = __ldcs(r + 1);
            if (okA) s0 = __ldcs(r - 1);
            if (okD) s3 = __ldcs(r + 2);
        }
        h[0] = 0.5f * (s0 + s1);
        h[1] = s1;
        h[2] = 0.5f * (s1 + s2);
        h[3] = s2;
        h[4] = 0.5f * (s2 + s3);
    }
    __device__ __forceinline__ void init(int n) {
        prev_y0 = (int)floorf(fmaf((float)n, 0.5f, -0.5f));
        load_row(prev_y0, ha);
        load_row(prev_y0 + 1, hb);
    }
    __device__ __forceinline__ float wy_adv(int n) {
        float y = fmaf((float)n, 0.5f, -0.5f);
        float y0f = floorf(y);
        int y0 = (int)y0f;
        if (y0 != prev_y0) {
#pragma unroll
            for (int k = 0; k < 5; k++) ha[k] = hb[k];
            load_row(y0 + 1, hb);
            prev_y0 = y0;
        }
        return y - y0f;
    }
};

static constexpr int CHT = 8;  // tiles per block (= 16 knot rows)

__global__ void __launch_bounds__(128) build_kernel(
    const float* __restrict__ l1, const float* __restrict__ l2,
    const float* __restrict__ l3, const float* __restrict__ l4) {
    int tcol = blockIdx.x * 128 + threadIdx.x;  // [0, 1023]
    int x4 = tcol * 4;                          // knot col base [0, 4092]
    int t_start = blockIdx.y * CHT;
    int t_end = min(t_start + CHT, 2049);
    if (t_start >= 2049) return;
    int n_start = 2 * t_start;

    L1S A;       A.setup(l1, x4);
    SL<1024> B;  B.setup(l2, x4);
    SL<512>  C;  C.setup(l3, x4);
    SL<256>  D;  D.setup(l4, x4);
    A.init(n_start); B.init(n_start); C.init(n_start); D.init(n_start);

    for (int t = t_start; t < t_end; t++) {
        int n0 = 2 * t;
        float K0[5], K1[5];
        {
            float wyA = A.wy_adv(n0);
            float wyB = B.wy_adv(n0);
            float wyC = C.wy_adv(n0);
            float wyD = D.wy_adv(n0);
#pragma unroll
            for (int k = 0; k < 5; k++) {
                float v = fmaf(wyA, A.hb[k] - A.ha[k], A.ha[k]);
                v += fmaf(wyB, B.hb[k] - B.ha[k], B.ha[k]);
                v += fmaf(wyC, C.hb[k] - C.ha[k], C.ha[k]);
                v += fmaf(wyD, D.hb[k] - D.ha[k], D.ha[k]);
                K0[k] = v;
            }
        }
        int n1 = n0 + 1;
        if (n1 <= 4096) {
            float wyA = A.wy_adv(n1);
            float wyB = B.wy_adv(n1);
            float wyC = C.wy_adv(n1);
            float wyD = D.wy_adv(n1);
#pragma unroll
            for (int k = 0; k < 5; k++) {
                float v = fmaf(wyA, A.hb[k] - A.ha[k], A.ha[k]);
                v += fmaf(wyB, B.hb[k] - B.ha[k], B.ha[k]);
                v += fmaf(wyC, C.hb[k] - C.ha[k], C.ha[k]);
                v += fmaf(wyD, D.hb[k] - D.ha[k], D.ha[k]);
                K1[k] = v;
            }
        } else {
#pragma unroll
            for (int k = 0; k < 5; k++) K1[k] = 0.f;
        }
        // 4 quads = 32B per thread, contiguous -> two 16B coalesced stores
        uint32_t p[8];
#pragma unroll
        for (int k = 0; k < 4; k++) {
            __half2 a = __floats2half2_rn(K0[k], K0[k + 1]);
            __half2 b = __floats2half2_rn(K1[k], K1[k + 1]);
            p[2 * k]     = *reinterpret_cast<uint32_t*>(&a);
            p[2 * k + 1] = *reinterpret_cast<uint32_t*>(&b);
        }
        uint4* dst = reinterpret_cast<uint4*>(g_Q + (long long)t * 4096 + x4);
        dst[0] = make_uint4(p[0], p[1], p[2], p[3]);
        dst[1] = make_uint4(p[4], p[5], p[6], p[7]);
    }
}

// ---- per-pixel sample: 1 quad load (even y0) or 2 (odd y0) ----
__device__ __forceinline__ float sample_px(float u, float v) {
    float xc = u * 4096.f, yc = v * 4096.f;
    int xi = max(0, min((int)xc, 4095));
    int yi = max(0, min((int)yc, 4095));
    float wx = xc - (float)xi, wy = yc - (float)yi;

    int t = yi >> 1;
    bool odd = yi & 1;
    int base = t * 4096 + xi;
    uint2 qa = __ldg(g_Q + base);
    float2 top, bot;
    if (odd) {
        uint2 qb = __ldg(g_Q + base + 4096);  // predicated second load
        top = h2f(qa.y);
        bot = h2f(qb.x);
    } else {
        top = h2f(qa.x);
        bot = h2f(qa.y);
    }
    float tv = fmaf(wx, top.y - top.x, top.x);
    float bv = fmaf(wx, bot.y - bot.x, bot.x);
    return fmaf(wy, bv - tv, tv);
}

__global__ void __launch_bounds__(256) gather_kernel(
    const float4* __restrict__ uv2, float2* __restrict__ out2, int npair) {
    int i = blockIdx.x * blockDim.x + threadIdx.x;
    if (i >= npair) return;
    float4 g = __ldcs(uv2 + i);
    float r0 = sample_px(g.x, g.y);
    float r1 = sample_px(g.z, g.w);
    __stcs(out2 + i, make_float2(r0, r1));
}

extern "C" void kernel_launch(void* const* d_in, const int* in_sizes, int n_in,
                              void* d_out, int out_size) {
    const float* uv = (const float*)d_in[0];
    const float* l1 = (const float*)d_in[1];  // 2048 x 2048
    const float* l2 = (const float*)d_in[2];  // 1024 x 1024
    const float* l3 = (const float*)d_in[3];  // 512  x 512
    const float* l4 = (const float*)d_in[4];  // 256  x 256

    build_kernel<<<dim3(8, (2049 + CHT - 1) / CHT), 128>>>(l1, l2, l3, l4);

    int npair = out_size / 2;  // 8*1024*1024 / 2
    gather_kernel<<<(npair + 255) / 256, 256>>>(
        (const float4*)uv, (float2*)d_out, npair);
}

// round 16
// speedup vs baseline: 1.0578x; 1.0578x over previous
#include <cuda_runtime.h>
#include <cuda_fp16.h>
#include <cstdint>

// ---------------------------------------------------------------------------
// LaplacianPyramid, unified-table with row-pair QUAD tiles.
//
// F = f1+f2+f3+f4 is exactly piecewise-bilinear on the uniform m/4096 uv-grid.
// Table: Q[t][x] = (K[2t][x], K[2t][x+1], K[2t+1][x], K[2t+1][x+1]) as 4xfp16
// (8 B, uint2). Even y0 pixels: ONE 8B load. Odd y0: two. Avg 1.5 sectors/px.
// Build: columnar march, CHT=4 tiles (8 rows) per block -> short serial
// dependence chain + 4104 blocks of cold-miss parallelism.
// ---------------------------------------------------------------------------

__device__ uint2 g_Q[2049 * 4096];  // 67.1 MB (tile 2048 row1 = zeros, unread)

__device__ __forceinline__ float2 h2f(uint32_t w) {
    __half2 h = *reinterpret_cast<__half2*>(&w);
    return __half22float2(h);
}

// ---- generic small layer (S in {1024,512,256}): 3 source cols ----
template <int S>
struct SL {
    const float* src;
    int c0;
    float wx[5];
    int tmask;
    bool ok0, ok1, ok2;
    float ha[5], hb[5];
    int prev_y0;

    __device__ __forceinline__ void setup(const float* s, int x4) {
        src = s;
        const float sc = (float)S / 4096.f;
        c0 = (int)floorf((float)x4 * sc - 0.5f);
        tmask = 0;
#pragma unroll
        for (int k = 0; k < 5; k++) {
            float xs = fmaf((float)(x4 + k), sc, -0.5f);
            float x0 = floorf(xs);
            wx[k] = xs - x0;
            if ((int)x0 != c0) tmask |= (1 << k);
        }
        ok0 = (c0 >= 0) & (c0 < S);
        ok1 = (c0 + 1 >= 0) & (c0 + 1 < S);
        ok2 = (c0 + 2 >= 0) & (c0 + 2 < S);
    }
    __device__ __forceinline__ void load_row(int row, float* h) {
        float s0 = 0.f, s1 = 0.f, s2 = 0.f;
        if (row >= 0 && row < S) {
            const float* r = src + (long long)row * S + c0;
            if (ok0) s0 = __ldcs(r);
            if (ok1) s1 = __ldcs(r + 1);
            if (ok2) s2 = __ldcs(r + 2);
        }
#pragma unroll
        for (int k = 0; k < 5; k++) {
            bool t = (tmask >> k) & 1;
            float v0 = t ? s1 : s0;
            float v1 = t ? s2 : s1;
            h[k] = fmaf(wx[k], v1 - v0, v0);
        }
    }
    __device__ __forceinline__ void init(int n) {
        const float sc = (float)S / 4096.f;
        prev_y0 = (int)floorf(fmaf((float)n, sc, -0.5f));
        load_row(prev_y0, ha);
        load_row(prev_y0 + 1, hb);
    }
    __device__ __forceinline__ float wy_adv(int n) {
        const float sc = (float)S / 4096.f;
        float y = fmaf((float)n, sc, -0.5f);
        float y0f = floorf(y);
        int y0 = (int)y0f;
        if (y0 != prev_y0) {
#pragma unroll
            for (int k = 0; k < 5; k++) ha[k] = hb[k];
            load_row(y0 + 1, hb);
            prev_y0 = y0;
        }
        return y - y0f;
    }
};

// ---- layer1 (S=2048): fixed copy/average pattern ----
struct L1S {
    const float* src;
    int j;
    bool okA, okD;
    float ha[5], hb[5];
    int prev_y0;

    __device__ __forceinline__ void setup(const float* s, int x4) {
        src = s;
        j = x4 >> 1;
        okA = (j - 1 >= 0);
        okD = (j + 2 < 2048);
    }
    __device__ __forceinline__ void load_row(int row, float* h) {
        float s0 = 0.f, s1 = 0.f, s2 = 0.f, s3 = 0.f;
        if (row >= 0 && row < 2048) {
            const float* r = src + (long long)row * 2048 + j;
            s1 = __ldcs(r);
            s2 = __ldcs(r + 1);
            if (okA) s0 = __ldcs(r - 1);
            if (okD) s3 = __ldcs(r + 2);
        }
        h[0] = 0.5f * (s0 + s1);
        h[1] = s1;
        h[2] = 0.5f * (s1 + s2);
        h[3] = s2;
        h[4] = 0.5f * (s2 + s3);
    }
    __device__ __forceinline__ void init(int n) {
        prev_y0 = (int)floorf(fmaf((float)n, 0.5f, -0.5f));
        load_row(prev_y0, ha);
        load_row(prev_y0 + 1, hb);
    }
    __device__ __forceinline__ float wy_adv(int n) {
        float y = fmaf((float)n, 0.5f, -0.5f);
        float y0f = floorf(y);
        int y0 = (int)y0f;
        if (y0 != prev_y0) {
#pragma unroll
            for (int k = 0; k < 5; k++) ha[k] = hb[k];
            load_row(y0 + 1, hb);
            prev_y0 = y0;
        }
        return y - y0f;
    }
};

static constexpr int CHT = 4;  // tiles per block (= 8 knot rows): short serial
                               // chain, 513 y-blocks of cold-miss parallelism

__global__ void __launch_bounds__(128) build_kernel(
    const float* __restrict__ l1, const float* __restrict__ l2,
    const float* __restrict__ l3, const float* __restrict__ l4) {
    int tcol = blockIdx.x * 128 + threadIdx.x;  // [0, 1023]
    int x4 = tcol * 4;                          // knot col base [0, 4092]
    int t_start = blockIdx.y * CHT;
    int t_end = min(t_start + CHT, 2049);
    if (t_start >= 2049) return;
    int n_start = 2 * t_start;

    L1S A;       A.setup(l1, x4);
    SL<1024> B;  B.setup(l2, x4);
    SL<512>  C;  C.setup(l3, x4);
    SL<256>  D;  D.setup(l4, x4);
    A.init(n_start); B.init(n_start); C.init(n_start); D.init(n_start);

    for (int t = t_start; t < t_end; t++) {
        int n0 = 2 * t;
        float K0[5], K1[5];
        {
            float wyA = A.wy_adv(n0);
            float wyB = B.wy_adv(n0);
            float wyC = C.wy_adv(n0);
            float wyD = D.wy_adv(n0);
#pragma unroll
            for (int k = 0; k < 5; k++) {
                float v = fmaf(wyA, A.hb[k] - A.ha[k], A.ha[k]);
                v += fmaf(wyB, B.hb[k] - B.ha[k], B.ha[k]);
                v += fmaf(wyC, C.hb[k] - C.ha[k], C.ha[k]);
                v += fmaf(wyD, D.hb[k] - D.ha[k], D.ha[k]);
                K0[k] = v;
            }
        }
        int n1 = n0 + 1;
        if (n1 <= 4096) {
            float wyA = A.wy_adv(n1);
            float wyB = B.wy_adv(n1);
            float wyC = C.wy_adv(n1);
            float wyD = D.wy_adv(n1);
#pragma unroll
            for (int k = 0; k < 5; k++) {
                float v = fmaf(wyA, A.hb[k] - A.ha[k], A.ha[k]);
                v += fmaf(wyB, B.hb[k] - B.ha[k], B.ha[k]);
                v += fmaf(wyC, C.hb[k] - C.ha[k], C.ha[k]);
                v += fmaf(wyD, D.hb[k] - D.ha[k], D.ha[k]);
                K1[k] = v;
            }
        } else {
#pragma unroll
            for (int k = 0; k < 5; k++) K1[k] = 0.f;
        }
        // 4 quads = 32B per thread, contiguous -> two 16B coalesced stores
        uint32_t p[8];
#pragma unroll
        for (int k = 0; k < 4; k++) {
            __half2 a = __floats2half2_rn(K0[k], K0[k + 1]);
            __half2 b = __floats2half2_rn(K1[k], K1[k + 1]);
            p[2 * k]     = *reinterpret_cast<uint32_t*>(&a);
            p[2 * k + 1] = *reinterpret_cast<uint32_t*>(&b);
        }
        uint4* dst = reinterpret_cast<uint4*>(g_Q + (long long)t * 4096 + x4);
        dst[0] = make_uint4(p[0], p[1], p[2], p[3]);
        dst[1] = make_uint4(p[4], p[5], p[6], p[7]);
    }
}

// ---- per-pixel sample: 1 quad load (even y0) or 2 (odd y0) ----
__device__ __forceinline__ float sample_px(float u, float v) {
    float xc = u * 4096.f, yc = v * 4096.f;
    int xi = max(0, min((int)xc, 4095));
    int yi = max(0, min((int)yc, 4095));
    float wx = xc - (float)xi, wy = yc - (float)yi;

    int t = yi >> 1;
    bool odd = yi & 1;
    int base = t * 4096 + xi;
    uint2 qa = __ldg(g_Q + base);
    float2 top, bot;
    if (odd) {
        uint2 qb = __ldg(g_Q + base + 4096);  // predicated second load
        top = h2f(qa.y);
        bot = h2f(qb.x);
    } else {
        top = h2f(qa.x);
        bot = h2f(qa.y);
    }
    float tv = fmaf(wx, top.y - top.x, top.x);
    float bv = fmaf(wx, bot.y - bot.x, bot.x);
    return fmaf(wy, bv - tv, tv);
}

__global__ void __launch_bounds__(256) gather_kernel(
    const float4* __restrict__ uv2, float2* __restrict__ out2, int npair) {
    int i = blockIdx.x * blockDim.x + threadIdx.x;
    if (i >= npair) return;
    float4 g = __ldcs(uv2 + i);
    float r0 = sample_px(g.x, g.y);
    float r1 = sample_px(g.z, g.w);
    __stcs(out2 + i, make_float2(r0, r1));
}

extern "C" void kernel_launch(void* const* d_in, const int* in_sizes, int n_in,
                              void* d_out, int out_size) {
    const float* uv = (const float*)d_in[0];
    const float* l1 = (const float*)d_in[1];  // 2048 x 2048
    const float* l2 = (const float*)d_in[2];  // 1024 x 1024
    const float* l3 = (const float*)d_in[3];  // 512  x 512
    const float* l4 = (const float*)d_in[4];  // 256  x 256

    build_kernel<<<dim3(8, (2049 + CHT - 1) / CHT), 128>>>(l1, l2, l3, l4);

    int npair = out_size / 2;  // 8*1024*1024 / 2
    gather_kernel<<<(npair + 255) / 256, 256>>>(
        (const float4*)uv, (float2*)d_out, npair);
}

// round 17
// speedup vs baseline: 1.1668x; 1.1030x over previous
#include <cuda_runtime.h>
#include <cuda_fp16.h>
#include <cstdint>

// ---------------------------------------------------------------------------
// LaplacianPyramid, unified-table with row-pair QUAD tiles.
//
// F = f1+f2+f3+f4 is exactly piecewise-bilinear on the uniform m/4096 uv-grid.
// Table: Q[t][x] = (K[2t][x], K[2t][x+1], K[2t+1][x], K[2t+1][x+1]) as 4xfp16
// (8 B, uint2). Even y0 pixels: ONE 8B load. Odd y0: two. Avg 1.5 sectors/px.
//
// Build (R17): 2 quads / 3 knots per thread -> ONE contiguous uint4 store
// per tile (warp = 512B contiguous), fixing the strided-store sector
// doubling that slowed the R15/R16 builds.
// ---------------------------------------------------------------------------

__device__ uint2 g_Q[2049 * 4096];  // 67.1 MB (tile 2048 row1 = zeros, unread)

__device__ __forceinline__ float2 h2f(uint32_t w) {
    __half2 h = *reinterpret_cast<__half2*>(&w);
    return __half22float2(h);
}

// ---- generic small layer (S in {1024,512,256}): 3 knots, 3 source cols ----
template <int S>
struct SL3 {
    const float* src;
    int c0;
    float wx[3];
    int tmask;
    bool ok0, ok1, ok2;
    float ha[3], hb[3];
    int prev_y0;

    __device__ __forceinline__ void setup(const float* s, int x2) {
        src = s;
        const float sc = (float)S / 4096.f;
        c0 = (int)floorf((float)x2 * sc - 0.5f);
        tmask = 0;
#pragma unroll
        for (int k = 0; k < 3; k++) {
            float xs = fmaf((float)(x2 + k), sc, -0.5f);
            float x0 = floorf(xs);
            wx[k] = xs - x0;
            if ((int)x0 != c0) tmask |= (1 << k);
        }
        ok0 = (c0 >= 0) & (c0 < S);
        ok1 = (c0 + 1 >= 0) & (c0 + 1 < S);
        ok2 = (c0 + 2 >= 0) & (c0 + 2 < S);
    }
    __device__ __forceinline__ void load_row(int row, float* h) {
        float s0 = 0.f, s1 = 0.f, s2 = 0.f;
        if (row >= 0 && row < S) {
            const float* r = src + (long long)row * S + c0;
            if (ok0) s0 = __ldcs(r);
            if (ok1) s1 = __ldcs(r + 1);
            if (ok2) s2 = __ldcs(r + 2);
        }
#pragma unroll
        for (int k = 0; k < 3; k++) {
            bool t = (tmask >> k) & 1;
            float v0 = t ? s1 : s0;
            float v1 = t ? s2 : s1;
            h[k] = fmaf(wx[k], v1 - v0, v0);
        }
    }
    __device__ __forceinline__ void init(int n) {
        const float sc = (float)S / 4096.f;
        prev_y0 = (int)floorf(fmaf((float)n, sc, -0.5f));
        load_row(prev_y0, ha);
        load_row(prev_y0 + 1, hb);
    }
    __device__ __forceinline__ float wy_adv(int n) {
        const float sc = (float)S / 4096.f;
        float y = fmaf((float)n, sc, -0.5f);
        float y0f = floorf(y);
        int y0 = (int)y0f;
        if (y0 != prev_y0) {
#pragma unroll
            for (int k = 0; k < 3; k++) ha[k] = hb[k];
            load_row(y0 + 1, hb);
            prev_y0 = y0;
        }
        return y - y0f;
    }
};

// ---- layer1 (S=2048): knots x2 (even), x2+1 (odd), x2+2 (even) ----
// even m: 0.5*(src[m/2-1]+src[m/2]); odd m: src[(m-1)/2]
struct L1S3 {
    const float* src;
    int j0;
    bool okA, okD;  // j0-1, j0+1 validity (j0 always valid)
    float ha[3], hb[3];
    int prev_y0;

    __device__ __forceinline__ void setup(const float* s, int x2) {
        src = s;
        j0 = x2 >> 1;  // [0, 2047]
        okA = (j0 - 1 >= 0);
        okD = (j0 + 1 < 2048);
    }
    __device__ __forceinline__ void load_row(int row, float* h) {
        float s0 = 0.f, s1 = 0.f, s2 = 0.f;
        if (row >= 0 && row < 2048) {
            const float* r = src + (long long)row * 2048 + j0;
            s1 = __ldcs(r);
            if (okA) s0 = __ldcs(r - 1);
            if (okD) s2 = __ldcs(r + 1);
        }
        h[0] = 0.5f * (s0 + s1);
        h[1] = s1;
        h[2] = 0.5f * (s1 + s2);
    }
    __device__ __forceinline__ void init(int n) {
        prev_y0 = (int)floorf(fmaf((float)n, 0.5f, -0.5f));
        load_row(prev_y0, ha);
        load_row(prev_y0 + 1, hb);
    }
    __device__ __forceinline__ float wy_adv(int n) {
        float y = fmaf((float)n, 0.5f, -0.5f);
        float y0f = floorf(y);
        int y0 = (int)y0f;
        if (y0 != prev_y0) {
#pragma unroll
            for (int k = 0; k < 3; k++) ha[k] = hb[k];
            load_row(y0 + 1, hb);
            prev_y0 = y0;
        }
        return y - y0f;
    }
};

static constexpr int CHT = 6;  // tiles per block (= 12 knot rows, R13 chain)

__global__ void __launch_bounds__(128) build_kernel(
    const float* __restrict__ l1, const float* __restrict__ l2,
    const float* __restrict__ l3, const float* __restrict__ l4) {
    int tcol = blockIdx.x * 128 + threadIdx.x;  // [0, 2047]
    int x2 = tcol * 2;                          // knot col base [0, 4094]
    int t_start = blockIdx.y * CHT;
    int t_end = min(t_start + CHT, 2049);
    if (t_start >= 2049) return;
    int n_start = 2 * t_start;

    L1S3 A;       A.setup(l1, x2);
    SL3<1024> B;  B.setup(l2, x2);
    SL3<512>  C;  C.setup(l3, x2);
    SL3<256>  D;  D.setup(l4, x2);
    A.init(n_start); B.init(n_start); C.init(n_start); D.init(n_start);

    for (int t = t_start; t < t_end; t++) {
        int n0 = 2 * t;
        float K0[3], K1[3];
        {
            float wyA = A.wy_adv(n0);
            float wyB = B.wy_adv(n0);
            float wyC = C.wy_adv(n0);
            float wyD = D.wy_adv(n0);
#pragma unroll
            for (int k = 0; k < 3; k++) {
                float v = fmaf(wyA, A.hb[k] - A.ha[k], A.ha[k]);
                v += fmaf(wyB, B.hb[k] - B.ha[k], B.ha[k]);
                v += fmaf(wyC, C.hb[k] - C.ha[k], C.ha[k]);
                v += fmaf(wyD, D.hb[k] - D.ha[k], D.ha[k]);
                K0[k] = v;
            }
        }
        int n1 = n0 + 1;
        if (n1 <= 4096) {
            float wyA = A.wy_adv(n1);
            float wyB = B.wy_adv(n1);
            float wyC = C.wy_adv(n1);
            float wyD = D.wy_adv(n1);
#pragma unroll
            for (int k = 0; k < 3; k++) {
                float v = fmaf(wyA, A.hb[k] - A.ha[k], A.ha[k]);
                v += fmaf(wyB, B.hb[k] - B.ha[k], B.ha[k]);
                v += fmaf(wyC, C.hb[k] - C.ha[k], C.ha[k]);
                v += fmaf(wyD, D.hb[k] - D.ha[k], D.ha[k]);
                K1[k] = v;
            }
        } else {
#pragma unroll
            for (int k = 0; k < 3; k++) K1[k] = 0.f;
        }
        // quads x2, x2+1 -> one 16B store, contiguous across lanes
        __half2 q0r0 = __floats2half2_rn(K0[0], K0[1]);
        __half2 q0r1 = __floats2half2_rn(K1[0], K1[1]);
        __half2 q1r0 = __floats2half2_rn(K0[1], K0[2]);
        __half2 q1r1 = __floats2half2_rn(K1[1], K1[2]);
        uint4 val = make_uint4(*reinterpret_cast<uint32_t*>(&q0r0),
                               *reinterpret_cast<uint32_t*>(&q0r1),
                               *reinterpret_cast<uint32_t*>(&q1r0),
                               *reinterpret_cast<uint32_t*>(&q1r1));
        *reinterpret_cast<uint4*>(g_Q + (long long)t * 4096 + x2) = val;
    }
}

// ---- per-pixel sample: 1 quad load (even y0) or 2 (odd y0) ----
__device__ __forceinline__ float sample_px(float u, float v) {
    float xc = u * 4096.f, yc = v * 4096.f;
    int xi = max(0, min((int)xc, 4095));
    int yi = max(0, min((int)yc, 4095));
    float wx = xc - (float)xi, wy = yc - (float)yi;

    int t = yi >> 1;
    bool odd = yi & 1;
    int base = t * 4096 + xi;
    uint2 qa = __ldg(g_Q + base);
    float2 top, bot;
    if (odd) {
        uint2 qb = __ldg(g_Q + base + 4096);  // predicated second load
        top = h2f(qa.y);
        bot = h2f(qb.x);
    } else {
        top = h2f(qa.x);
        bot = h2f(qa.y);
    }
    float tv = fmaf(wx, top.y - top.x, top.x);
    float bv = fmaf(wx, bot.y - bot.x, bot.x);
    return fmaf(wy, bv - tv, tv);
}

__global__ void __launch_bounds__(256) gather_kernel(
    const float4* __restrict__ uv2, float2* __restrict__ out2, int npair) {
    int i = blockIdx.x * blockDim.x + threadIdx.x;
    if (i >= npair) return;
    float4 g = __ldcs(uv2 + i);
    float r0 = sample_px(g.x, g.y);
    float r1 = sample_px(g.z, g.w);
    __stcs(out2 + i, make_float2(r0, r1));
}

extern "C" void kernel_launch(void* const* d_in, const int* in_sizes, int n_in,
                              void* d_out, int out_size) {
    const float* uv = (const float*)d_in[0];
    const float* l1 = (const float*)d_in[1];  // 2048 x 2048
    const float* l2 = (const float*)d_in[2];  // 1024 x 1024
    const float* l3 = (const float*)d_in[3];  // 512  x 512
    const float* l4 = (const float*)d_in[4];  // 256  x 256

    build_kernel<<<dim3(16, (2049 + CHT - 1) / CHT), 128>>>(l1, l2, l3, l4);

    int npair = out_size / 2;  // 8*1024*1024 / 2
    gather_kernel<<<(npair + 255) / 256, 256>>>(
        (const float4*)uv, (float2*)d_out, npair);
}